// round 5
// baseline (speedup 1.0000x reference)
#include <cuda_runtime.h>
#include <cuda_bf16.h>

#define NMAX 16384
#define FDIM 32
#define KDIM 16

// Scratch (no allocations allowed) — N is fixed at 16384 by the problem setup.
__device__ __align__(16) float g_x0[NMAX * FDIM];
__device__ __align__(16) float g_y[NMAX * FDIM];
__device__ float g_epair[NMAX];
__device__ __align__(16) float g_Wc[KDIM * FDIM];

__device__ __forceinline__ void red4(float* addr, float a, float b, float c, float d) {
#if defined(__CUDA_ARCH__) && (__CUDA_ARCH__ >= 900)
    atomicAdd(reinterpret_cast<float4*>(addr), make_float4(a, b, c, d));
#else
    atomicAdd(addr + 0, a); atomicAdd(addr + 1, b);
    atomicAdd(addr + 2, c); atomicAdd(addr + 3, d);
#endif
}

// Zero all accumulators + output; build combined weight Wc = 0.282095*Wr1_0 + Wr2_0
__global__ void init_kernel(float* __restrict__ out, int B,
                            const float* __restrict__ Wr10,
                            const float* __restrict__ Wr20, int N) {
    int i = blockIdx.x * blockDim.x + threadIdx.x;
    int tot = N * FDIM;
    if (i < tot) { g_x0[i] = 0.0f; g_y[i] = 0.0f; }
    if (i < N) g_epair[i] = 0.0f;
    if (i < B) out[i] = 0.0f;
    if (i < KDIM * FDIM) g_Wc[i] = 0.282095f * Wr10[i] + Wr20[i];
}

// One warp handles 4 edges; each lane owns 4 feature channels of one edge.
// PASS=1: accum g_x0 += (rad@Wc) * emb[Z[src]] ; also ZBL pair energy -> g_epair
// PASS=2: accum g_y  += (rad@Wr1_1) * g_x0[src]
template <int PASS>
__global__ void __launch_bounds__(256) edge_kernel(
    const float* __restrict__ pos,
    const int*   __restrict__ dst,
    const int*   __restrict__ src,
    const int*   __restrict__ Z,
    const float* __restrict__ emb,    // used for PASS=1
    const float* __restrict__ Wext,   // Wr1_1 for PASS=2
    int E) {
    __shared__ float sW[KDIM * FDIM];
    if (PASS == 1) {
        for (int i = threadIdx.x; i < KDIM * FDIM; i += blockDim.x) sW[i] = g_Wc[i];
    } else {
        for (int i = threadIdx.x; i < KDIM * FDIM; i += blockDim.x) sW[i] = Wext[i];
    }
    __syncthreads();

    int gtid = blockIdx.x * blockDim.x + threadIdx.x;
    int warp = gtid >> 5;
    int lane = threadIdx.x & 31;
    int e = warp * 4 + (lane >> 3);
    if (e >= E) return;
    int fg = (lane & 7) * 4;

    int d = __ldg(&dst[e]);
    int s = __ldg(&src[e]);
    float dx = __ldg(&pos[s * 3 + 0]) - __ldg(&pos[d * 3 + 0]);
    float dy = __ldg(&pos[s * 3 + 1]) - __ldg(&pos[d * 3 + 1]);
    float dz = __ldg(&pos[s * 3 + 2]) - __ldg(&pos[d * 3 + 2]);
    float r = sqrtf(dx * dx + dy * dy + dz * dz + 1e-10f);
    r = fmaxf(r, 1e-4f);
    // Beyond cutoff every contribution (rad and e_pair) is exactly 0 — skip.
    if (r >= 6.0f) return;

    float u = r * (1.0f / 6.0f);
    float cut = expf(-u * u / (1.0f - u * u));
    float tt = 2.0f * expf(-r) - 1.0f;
    tt = fminf(fmaxf(tt, -1.0f), 1.0f);

    // rad[k] = T_k(tt) * cut ; g[f] = sum_k rad[k]*W[k][f]  (cut factored out)
    const float4* w4 = reinterpret_cast<const float4*>(&sW[fg]); // row stride = 8 float4
    float4 w = w4[0];
    float a0 = w.x, a1 = w.y, a2 = w.z, a3 = w.w;
    w = w4[8];
    a0 = fmaf(tt, w.x, a0); a1 = fmaf(tt, w.y, a1);
    a2 = fmaf(tt, w.z, a2); a3 = fmaf(tt, w.w, a3);
    float Tp = 1.0f, Tc = tt;
#pragma unroll
    for (int k = 2; k < KDIM; k++) {
        float Tn = 2.0f * tt * Tc - Tp; Tp = Tc; Tc = Tn;
        w = w4[8 * k];
        a0 = fmaf(Tn, w.x, a0); a1 = fmaf(Tn, w.y, a1);
        a2 = fmaf(Tn, w.z, a2); a3 = fmaf(Tn, w.w, a3);
    }
    a0 *= cut; a1 *= cut; a2 *= cut; a3 *= cut;

    int z = 0;
    float4 v;
    if (PASS == 1) {
        z = __ldg(&Z[s]);
        v = __ldg(reinterpret_cast<const float4*>(&emb[z * FDIM + fg]));
    } else {
        v = *reinterpret_cast<const float4*>(&g_x0[s * FDIM + fg]);
    }

    if (PASS == 1) {
        red4(&g_x0[d * FDIM + fg], a0 * v.x, a1 * v.y, a2 * v.z, a3 * v.w);
        if ((lane & 7) == 0) {
            // ZBL pair energy (one lane per edge)
            float zdf = (float)__ldg(&Z[d]);
            float zsf = (float)z;
            float aa = 0.46853332f / (powf(zdf, 0.23f) + powf(zsf, 0.23f) + 1e-10f);
            float ra = r / aa;
            float phi = 0.18175f * expf(-3.1998f  * ra)
                      + 0.50986f * expf(-0.94229f * ra)
                      + 0.28022f * expf(-0.4029f  * ra)
                      + 0.02817f * expf(-0.20162f * ra);
            float ep = 0.5f * 14.399645f * zdf * zsf / r * phi * cut;
            atomicAdd(&g_epair[d], ep);
        }
    } else {
        red4(&g_y[d * FDIM + fg], a0 * v.x, a1 * v.y, a2 * v.z, a3 * v.w);
    }
}

// x0 = x0 + (h * silu(h)) @ W2_0,  h = x0 @ W1_0   (in place on g_x0)
__global__ void __launch_bounds__(256) mlp1_kernel(
    const float* __restrict__ W1, const float* __restrict__ W2, int N) {
    __shared__ float s1[FDIM * FDIM], s2[FDIM * FDIM];
    for (int i = threadIdx.x; i < FDIM * FDIM; i += blockDim.x) {
        s1[i] = W1[i]; s2[i] = W2[i];
    }
    __syncthreads();
    int n = blockIdx.x * blockDim.x + threadIdx.x;
    if (n >= N) return;

    float x[FDIM], t[FDIM];
#pragma unroll
    for (int f = 0; f < FDIM; f += 4) {
        float4 v = *reinterpret_cast<const float4*>(&g_x0[n * FDIM + f]);
        x[f] = v.x; x[f + 1] = v.y; x[f + 2] = v.z; x[f + 3] = v.w;
    }
#pragma unroll
    for (int gb = 0; gb < FDIM; gb += 4) {
        float h0 = 0.f, h1 = 0.f, h2 = 0.f, h3 = 0.f;
#pragma unroll
        for (int f = 0; f < FDIM; f++) {
            float4 wv = *reinterpret_cast<const float4*>(&s1[f * FDIM + gb]);
            h0 = fmaf(x[f], wv.x, h0); h1 = fmaf(x[f], wv.y, h1);
            h2 = fmaf(x[f], wv.z, h2); h3 = fmaf(x[f], wv.w, h3);
        }
        // h * silu(h) = h^2 * sigmoid(h)
        t[gb]     = h0 * h0 / (1.0f + expf(-h0));
        t[gb + 1] = h1 * h1 / (1.0f + expf(-h1));
        t[gb + 2] = h2 * h2 / (1.0f + expf(-h2));
        t[gb + 3] = h3 * h3 / (1.0f + expf(-h3));
    }
#pragma unroll
    for (int gb = 0; gb < FDIM; gb += 4) {
        float o0 = x[gb], o1 = x[gb + 1], o2 = x[gb + 2], o3 = x[gb + 3];
#pragma unroll
        for (int f = 0; f < FDIM; f++) {
            float4 wv = *reinterpret_cast<const float4*>(&s2[f * FDIM + gb]);
            o0 = fmaf(t[f], wv.x, o0); o1 = fmaf(t[f], wv.y, o1);
            o2 = fmaf(t[f], wv.z, o2); o3 = fmaf(t[f], wv.w, o3);
        }
        *reinterpret_cast<float4*>(&g_x0[n * FDIM + gb]) = make_float4(o0, o1, o2, o3);
    }
}

// y2 = y + silu(y@W1_1)@W2_1 ; e = y2.w_out + b_out[Z] + epair; masked; atomic into out[batch]
__global__ void __launch_bounds__(256) final_kernel(
    const float* __restrict__ W1, const float* __restrict__ W2,
    const float* __restrict__ wout, const float* __restrict__ bout,
    const int* __restrict__ Z, const int* __restrict__ bseg,
    const float* __restrict__ amask, const float* __restrict__ bmask,
    float* __restrict__ out, int N) {
    __shared__ float s1[FDIM * FDIM], s2[FDIM * FDIM], sw[FDIM];
    for (int i = threadIdx.x; i < FDIM * FDIM; i += blockDim.x) {
        s1[i] = W1[i]; s2[i] = W2[i];
    }
    if (threadIdx.x < FDIM) sw[threadIdx.x] = wout[threadIdx.x];
    __syncthreads();
    int n = blockIdx.x * blockDim.x + threadIdx.x;
    if (n >= N) return;

    float y[FDIM], t[FDIM];
#pragma unroll
    for (int f = 0; f < FDIM; f += 4) {
        float4 v = *reinterpret_cast<const float4*>(&g_y[n * FDIM + f]);
        y[f] = v.x; y[f + 1] = v.y; y[f + 2] = v.z; y[f + 3] = v.w;
    }
#pragma unroll
    for (int gb = 0; gb < FDIM; gb += 4) {
        float h0 = 0.f, h1 = 0.f, h2 = 0.f, h3 = 0.f;
#pragma unroll
        for (int f = 0; f < FDIM; f++) {
            float4 wv = *reinterpret_cast<const float4*>(&s1[f * FDIM + gb]);
            h0 = fmaf(y[f], wv.x, h0); h1 = fmaf(y[f], wv.y, h1);
            h2 = fmaf(y[f], wv.z, h2); h3 = fmaf(y[f], wv.w, h3);
        }
        // silu(h) = h * sigmoid(h)
        t[gb]     = h0 / (1.0f + expf(-h0));
        t[gb + 1] = h1 / (1.0f + expf(-h1));
        t[gb + 2] = h2 / (1.0f + expf(-h2));
        t[gb + 3] = h3 / (1.0f + expf(-h3));
    }
    float e = 0.0f;
#pragma unroll
    for (int gb = 0; gb < FDIM; gb += 4) {
        float o0 = y[gb], o1 = y[gb + 1], o2 = y[gb + 2], o3 = y[gb + 3];
#pragma unroll
        for (int f = 0; f < FDIM; f++) {
            float4 wv = *reinterpret_cast<const float4*>(&s2[f * FDIM + gb]);
            o0 = fmaf(t[f], wv.x, o0); o1 = fmaf(t[f], wv.y, o1);
            o2 = fmaf(t[f], wv.z, o2); o3 = fmaf(t[f], wv.w, o3);
        }
        e = fmaf(o0, sw[gb], e);
        e = fmaf(o1, sw[gb + 1], e);
        e = fmaf(o2, sw[gb + 2], e);
        e = fmaf(o3, sw[gb + 3], e);
    }
    e += __ldg(&bout[__ldg(&Z[n])]) + g_epair[n];
    e *= __ldg(&amask[n]);
    int b = __ldg(&bseg[n]);
    atomicAdd(&out[b], e * __ldg(&bmask[b]));
}

extern "C" void kernel_launch(void* const* d_in, const int* in_sizes, int n_in,
                              void* d_out, int out_size) {
    const int*   Z     = (const int*)d_in[0];
    const float* pos   = (const float*)d_in[1];
    const int*   dst   = (const int*)d_in[2];
    const int*   src   = (const int*)d_in[3];
    const int*   bseg  = (const int*)d_in[4];
    // 'batch_size' may or may not be materialized as a size-1 input at index 5.
    int off = (in_sizes[5] == 1) ? 1 : 0;
    const float* bmask = (const float*)d_in[5 + off];
    const float* amask = (const float*)d_in[6 + off];
    const float* emb   = (const float*)d_in[7 + off];
    const float* Wr1_0 = (const float*)d_in[8 + off];
    const float* Wr2_0 = (const float*)d_in[9 + off];
    const float* W1_0  = (const float*)d_in[10 + off];
    const float* W2_0  = (const float*)d_in[11 + off];
    const float* Wr1_1 = (const float*)d_in[12 + off];
    const float* W1_1  = (const float*)d_in[13 + off];
    const float* W2_1  = (const float*)d_in[14 + off];
    const float* wout  = (const float*)d_in[15 + off];
    const float* bout  = (const float*)d_in[16 + off];

    int N = in_sizes[0];
    int E = in_sizes[2];
    int B = out_size;
    float* out = (float*)d_out;

    init_kernel<<<(N * FDIM + 255) / 256, 256>>>(out, B, Wr1_0, Wr2_0, N);

    int eblocks = (E + 31) / 32;  // 32 edges per 256-thread block (4 edges/warp)
    edge_kernel<1><<<eblocks, 256>>>(pos, dst, src, Z, emb, nullptr, E);

    mlp1_kernel<<<(N + 255) / 256, 256>>>(W1_0, W2_0, N);

    edge_kernel<2><<<eblocks, 256>>>(pos, dst, src, Z, emb, Wr1_1, E);

    final_kernel<<<(N + 255) / 256, 256>>>(W1_1, W2_1, wout, bout, Z, bseg,
                                           amask, bmask, out, N);
}

// round 6
// speedup vs baseline: 1.0506x; 1.0506x over previous
#include <cuda_runtime.h>
#include <cuda_bf16.h>

#define NMAX 16384
#define FDIM 32
#define KDIM 16

// Scratch (no allocations allowed) — N is fixed at 16384 by the problem setup.
__device__ __align__(16) float g_x0[NMAX * FDIM];
__device__ __align__(16) float g_y[NMAX * FDIM];
__device__ float g_epair[NMAX];
__device__ __align__(16) float g_Wc[KDIM * FDIM];

__device__ __forceinline__ void red4(float* addr, float a, float b, float c, float d) {
#if defined(__CUDA_ARCH__) && (__CUDA_ARCH__ >= 900)
    atomicAdd(reinterpret_cast<float4*>(addr), make_float4(a, b, c, d));
#else
    atomicAdd(addr + 0, a); atomicAdd(addr + 1, b);
    atomicAdd(addr + 2, c); atomicAdd(addr + 3, d);
#endif
}

// Zero all accumulators + output; build combined weight Wc = 0.282095*Wr1_0 + Wr2_0
__global__ void init_kernel(float* __restrict__ out, int B,
                            const float* __restrict__ Wr10,
                            const float* __restrict__ Wr20, int N) {
    int i = blockIdx.x * blockDim.x + threadIdx.x;
    int tot = N * FDIM;
    if (i < tot) { g_x0[i] = 0.0f; g_y[i] = 0.0f; }
    if (i < N) g_epair[i] = 0.0f;
    if (i < B) out[i] = 0.0f;
    if (i < KDIM * FDIM) g_Wc[i] = 0.282095f * Wr10[i] + Wr20[i];
}

// One warp handles 4 edges; each lane owns 4 feature channels of one edge.
// PASS=1: accum g_x0 += (rad@Wc) * emb[Z[src]] ; also ZBL pair energy -> g_epair
// PASS=2: accum g_y  += (rad@Wr1_1) * g_x0[src]
template <int PASS>
__global__ void __launch_bounds__(256) edge_kernel(
    const float* __restrict__ pos,
    const int*   __restrict__ dst,
    const int*   __restrict__ src,
    const int*   __restrict__ Z,
    const float* __restrict__ emb,    // used for PASS=1
    const float* __restrict__ Wext,   // Wr1_1 for PASS=2
    int E) {
    __shared__ float sW[KDIM * FDIM];
    if (PASS == 1) {
        for (int i = threadIdx.x; i < KDIM * FDIM; i += blockDim.x) sW[i] = g_Wc[i];
    } else {
        for (int i = threadIdx.x; i < KDIM * FDIM; i += blockDim.x) sW[i] = Wext[i];
    }
    __syncthreads();

    int gtid = blockIdx.x * blockDim.x + threadIdx.x;
    int warp = gtid >> 5;
    int lane = threadIdx.x & 31;
    int e = warp * 4 + (lane >> 3);
    if (e >= E) return;
    int fg = (lane & 7) * 4;

    int d = __ldg(&dst[e]);
    int s = __ldg(&src[e]);
    float dx = __ldg(&pos[s * 3 + 0]) - __ldg(&pos[d * 3 + 0]);
    float dy = __ldg(&pos[s * 3 + 1]) - __ldg(&pos[d * 3 + 1]);
    float dz = __ldg(&pos[s * 3 + 2]) - __ldg(&pos[d * 3 + 2]);
    float r = sqrtf(dx * dx + dy * dy + dz * dz + 1e-10f);
    r = fmaxf(r, 1e-4f);
    // Beyond cutoff every contribution (rad and e_pair) is exactly 0 — skip.
    if (r >= 6.0f) return;

    float u = r * (1.0f / 6.0f);
    float cut = expf(-u * u / (1.0f - u * u));
    float tt = 2.0f * expf(-r) - 1.0f;
    tt = fminf(fmaxf(tt, -1.0f), 1.0f);

    // rad[k] = T_k(tt) * cut ; g[f] = sum_k rad[k]*W[k][f]  (cut factored out)
    const float4* w4 = reinterpret_cast<const float4*>(&sW[fg]); // row stride = 8 float4
    float4 w = w4[0];
    float a0 = w.x, a1 = w.y, a2 = w.z, a3 = w.w;
    w = w4[8];
    a0 = fmaf(tt, w.x, a0); a1 = fmaf(tt, w.y, a1);
    a2 = fmaf(tt, w.z, a2); a3 = fmaf(tt, w.w, a3);
    float Tp = 1.0f, Tc = tt;
#pragma unroll
    for (int k = 2; k < KDIM; k++) {
        float Tn = 2.0f * tt * Tc - Tp; Tp = Tc; Tc = Tn;
        w = w4[8 * k];
        a0 = fmaf(Tn, w.x, a0); a1 = fmaf(Tn, w.y, a1);
        a2 = fmaf(Tn, w.z, a2); a3 = fmaf(Tn, w.w, a3);
    }
    a0 *= cut; a1 *= cut; a2 *= cut; a3 *= cut;

    int z = 0;
    float4 v;
    if (PASS == 1) {
        z = __ldg(&Z[s]);
        v = __ldg(reinterpret_cast<const float4*>(&emb[z * FDIM + fg]));
    } else {
        v = *reinterpret_cast<const float4*>(&g_x0[s * FDIM + fg]);
    }

    if (PASS == 1) {
        red4(&g_x0[d * FDIM + fg], a0 * v.x, a1 * v.y, a2 * v.z, a3 * v.w);
        if ((lane & 7) == 0) {
            // ZBL pair energy (one lane per edge)
            float zdf = (float)__ldg(&Z[d]);
            float zsf = (float)z;
            float aa = 0.46853332f / (powf(zdf, 0.23f) + powf(zsf, 0.23f) + 1e-10f);
            float ra = r / aa;
            float phi = 0.18175f * expf(-3.1998f  * ra)
                      + 0.50986f * expf(-0.94229f * ra)
                      + 0.28022f * expf(-0.4029f  * ra)
                      + 0.02817f * expf(-0.20162f * ra);
            float ep = 0.5f * 14.399645f * zdf * zsf / r * phi * cut;
            atomicAdd(&g_epair[d], ep);
        }
    } else {
        red4(&g_y[d * FDIM + fg], a0 * v.x, a1 * v.y, a2 * v.z, a3 * v.w);
    }
}

// x0 = x0 + (h * silu(h)) @ W2_0,  h = x0 @ W1_0   (in place on g_x0)
__global__ void __launch_bounds__(256) mlp1_kernel(
    const float* __restrict__ W1, const float* __restrict__ W2, int N) {
    __shared__ float s1[FDIM * FDIM], s2[FDIM * FDIM];
    for (int i = threadIdx.x; i < FDIM * FDIM; i += blockDim.x) {
        s1[i] = W1[i]; s2[i] = W2[i];
    }
    __syncthreads();
    int n = blockIdx.x * blockDim.x + threadIdx.x;
    if (n >= N) return;

    float x[FDIM], t[FDIM];
#pragma unroll
    for (int f = 0; f < FDIM; f += 4) {
        float4 v = *reinterpret_cast<const float4*>(&g_x0[n * FDIM + f]);
        x[f] = v.x; x[f + 1] = v.y; x[f + 2] = v.z; x[f + 3] = v.w;
    }
#pragma unroll
    for (int gb = 0; gb < FDIM; gb += 4) {
        float h0 = 0.f, h1 = 0.f, h2 = 0.f, h3 = 0.f;
#pragma unroll
        for (int f = 0; f < FDIM; f++) {
            float4 wv = *reinterpret_cast<const float4*>(&s1[f * FDIM + gb]);
            h0 = fmaf(x[f], wv.x, h0); h1 = fmaf(x[f], wv.y, h1);
            h2 = fmaf(x[f], wv.z, h2); h3 = fmaf(x[f], wv.w, h3);
        }
        // h * silu(h) = h^2 * sigmoid(h)
        t[gb]     = h0 * h0 / (1.0f + expf(-h0));
        t[gb + 1] = h1 * h1 / (1.0f + expf(-h1));
        t[gb + 2] = h2 * h2 / (1.0f + expf(-h2));
        t[gb + 3] = h3 * h3 / (1.0f + expf(-h3));
    }
#pragma unroll
    for (int gb = 0; gb < FDIM; gb += 4) {
        float o0 = x[gb], o1 = x[gb + 1], o2 = x[gb + 2], o3 = x[gb + 3];
#pragma unroll
        for (int f = 0; f < FDIM; f++) {
            float4 wv = *reinterpret_cast<const float4*>(&s2[f * FDIM + gb]);
            o0 = fmaf(t[f], wv.x, o0); o1 = fmaf(t[f], wv.y, o1);
            o2 = fmaf(t[f], wv.z, o2); o3 = fmaf(t[f], wv.w, o3);
        }
        *reinterpret_cast<float4*>(&g_x0[n * FDIM + gb]) = make_float4(o0, o1, o2, o3);
    }
}

// y2 = y + silu(y@W1_1)@W2_1 ; e = y2.w_out + b_out[Z] + epair; masked; atomic into out[batch]
__global__ void __launch_bounds__(256) final_kernel(
    const float* __restrict__ W1, const float* __restrict__ W2,
    const float* __restrict__ wout, const float* __restrict__ bout,
    const int* __restrict__ Z, const int* __restrict__ bseg,
    const float* __restrict__ amask, const float* __restrict__ bmask,
    float* __restrict__ out, int N) {
    __shared__ float s1[FDIM * FDIM], s2[FDIM * FDIM], sw[FDIM];
    for (int i = threadIdx.x; i < FDIM * FDIM; i += blockDim.x) {
        s1[i] = W1[i]; s2[i] = W2[i];
    }
    if (threadIdx.x < FDIM) sw[threadIdx.x] = wout[threadIdx.x];
    __syncthreads();
    int n = blockIdx.x * blockDim.x + threadIdx.x;
    if (n >= N) return;

    float y[FDIM], t[FDIM];
#pragma unroll
    for (int f = 0; f < FDIM; f += 4) {
        float4 v = *reinterpret_cast<const float4*>(&g_y[n * FDIM + f]);
        y[f] = v.x; y[f + 1] = v.y; y[f + 2] = v.z; y[f + 3] = v.w;
    }
#pragma unroll
    for (int gb = 0; gb < FDIM; gb += 4) {
        float h0 = 0.f, h1 = 0.f, h2 = 0.f, h3 = 0.f;
#pragma unroll
        for (int f = 0; f < FDIM; f++) {
            float4 wv = *reinterpret_cast<const float4*>(&s1[f * FDIM + gb]);
            h0 = fmaf(y[f], wv.x, h0); h1 = fmaf(y[f], wv.y, h1);
            h2 = fmaf(y[f], wv.z, h2); h3 = fmaf(y[f], wv.w, h3);
        }
        // silu(h) = h * sigmoid(h)
        t[gb]     = h0 / (1.0f + expf(-h0));
        t[gb + 1] = h1 / (1.0f + expf(-h1));
        t[gb + 2] = h2 / (1.0f + expf(-h2));
        t[gb + 3] = h3 / (1.0f + expf(-h3));
    }
    float e = 0.0f;
#pragma unroll
    for (int gb = 0; gb < FDIM; gb += 4) {
        float o0 = y[gb], o1 = y[gb + 1], o2 = y[gb + 2], o3 = y[gb + 3];
#pragma unroll
        for (int f = 0; f < FDIM; f++) {
            float4 wv = *reinterpret_cast<const float4*>(&s2[f * FDIM + gb]);
            o0 = fmaf(t[f], wv.x, o0); o1 = fmaf(t[f], wv.y, o1);
            o2 = fmaf(t[f], wv.z, o2); o3 = fmaf(t[f], wv.w, o3);
        }
        e = fmaf(o0, sw[gb], e);
        e = fmaf(o1, sw[gb + 1], e);
        e = fmaf(o2, sw[gb + 2], e);
        e = fmaf(o3, sw[gb + 3], e);
    }
    e += __ldg(&bout[__ldg(&Z[n])]) + g_epair[n];
    e *= __ldg(&amask[n]);
    int b = __ldg(&bseg[n]);
    atomicAdd(&out[b], e * __ldg(&bmask[b]));
}

extern "C" void kernel_launch(void* const* d_in, const int* in_sizes, int n_in,
                              void* d_out, int out_size) {
    const int*   Z     = (const int*)d_in[0];
    const float* pos   = (const float*)d_in[1];
    const int*   dst   = (const int*)d_in[2];
    const int*   src   = (const int*)d_in[3];
    const int*   bseg  = (const int*)d_in[4];
    // 'batch_size' may or may not be materialized as a size-1 input at index 5.
    int off = (in_sizes[5] == 1) ? 1 : 0;
    const float* bmask = (const float*)d_in[5 + off];
    const float* amask = (const float*)d_in[6 + off];
    const float* emb   = (const float*)d_in[7 + off];
    const float* Wr1_0 = (const float*)d_in[8 + off];
    const float* Wr2_0 = (const float*)d_in[9 + off];
    const float* W1_0  = (const float*)d_in[10 + off];
    const float* W2_0  = (const float*)d_in[11 + off];
    const float* Wr1_1 = (const float*)d_in[12 + off];
    const float* W1_1  = (const float*)d_in[13 + off];
    const float* W2_1  = (const float*)d_in[14 + off];
    const float* wout  = (const float*)d_in[15 + off];
    const float* bout  = (const float*)d_in[16 + off];

    int N = in_sizes[0];
    int E = in_sizes[2];
    int B = out_size;
    float* out = (float*)d_out;

    init_kernel<<<(N * FDIM + 255) / 256, 256>>>(out, B, Wr1_0, Wr2_0, N);

    int eblocks = (E + 31) / 32;  // 32 edges per 256-thread block (4 edges/warp)
    edge_kernel<1><<<eblocks, 256>>>(pos, dst, src, Z, emb, nullptr, E);

    mlp1_kernel<<<(N + 255) / 256, 256>>>(W1_0, W2_0, N);

    edge_kernel<2><<<eblocks, 256>>>(pos, dst, src, Z, emb, Wr1_1, E);

    final_kernel<<<(N + 255) / 256, 256>>>(W1_1, W2_1, wout, bout, Z, bseg,
                                           amask, bmask, out, N);
}

// round 7
// speedup vs baseline: 1.4675x; 1.3968x over previous
#include <cuda_runtime.h>
#include <cuda_bf16.h>

#define NMAX 16384
#define FDIM 32
#define KDIM 16

// Scratch (no allocations allowed) — N is fixed at 16384 by the problem setup.
__device__ __align__(16) float g_x0[NMAX * FDIM];
__device__ __align__(16) float g_y[NMAX * FDIM];
__device__ float g_epair[NMAX];
__device__ __align__(16) float g_Wc[KDIM * FDIM];

__device__ __forceinline__ void red4(float* addr, float a, float b, float c, float d) {
    atomicAdd(reinterpret_cast<float4*>(addr), make_float4(a, b, c, d));
}

// Zero all accumulators + output; build combined weight Wc = 0.282095*Wr1_0 + Wr2_0
__global__ void init_kernel(float* __restrict__ out, int B,
                            const float* __restrict__ Wr10,
                            const float* __restrict__ Wr20, int N) {
    int i = blockIdx.x * blockDim.x + threadIdx.x;
    int tot4 = N * FDIM / 4;
    float4 z4 = make_float4(0.f, 0.f, 0.f, 0.f);
    if (i < tot4) {
        reinterpret_cast<float4*>(g_x0)[i] = z4;
        reinterpret_cast<float4*>(g_y)[i] = z4;
    }
    if (i < N) g_epair[i] = 0.0f;
    if (i < B) out[i] = 0.0f;
    if (i < KDIM * FDIM) g_Wc[i] = 0.282095f * Wr10[i] + Wr20[i];
}

// Edge pass, two phases per warp:
//   Scalar phase: 32 edges/warp (1/lane). Loads + distance + cutoff + tt,
//                 (PASS 1 also: ZBL pair energy -> g_epair, once per edge).
//   Feature phase: ballot-compact the valid edges, process 4 at a time
//                 (octet of lanes per edge, 4 channels per lane), red4 scatter.
// PASS=1: g_x0 += (rad@Wc)   * emb[Z[src]]
// PASS=2: g_y  += (rad@Wr1_1) * g_x0[src]
template <int PASS>
__global__ void __launch_bounds__(256) edge_kernel(
    const float* __restrict__ pos,
    const int*   __restrict__ dst,
    const int*   __restrict__ src,
    const int*   __restrict__ Z,
    const float* __restrict__ emb,    // used for PASS=1
    const float* __restrict__ Wext,   // Wr1_1 for PASS=2
    int E) {
    __shared__ float sW[KDIM * FDIM];
    if (PASS == 1) {
        for (int i = threadIdx.x; i < KDIM * FDIM; i += blockDim.x) sW[i] = g_Wc[i];
    } else {
        for (int i = threadIdx.x; i < KDIM * FDIM; i += blockDim.x) sW[i] = Wext[i];
    }
    __syncthreads();

    int lane = threadIdx.x & 31;
    int warp_global = (blockIdx.x * blockDim.x + threadIdx.x) >> 5;
    int ebase = warp_global * 32;
    if (ebase >= E) return;   // uniform per warp

    // ---- scalar phase: one edge per lane ----
    int e = ebase + lane;
    bool valid = false;
    float tt = 0.0f, cut = 0.0f;
    int d = 0, s = 0, zs = 0;
    if (e < E) {
        d = __ldg(&dst[e]);
        s = __ldg(&src[e]);
        float dx = __ldg(&pos[s * 3 + 0]) - __ldg(&pos[d * 3 + 0]);
        float dy = __ldg(&pos[s * 3 + 1]) - __ldg(&pos[d * 3 + 1]);
        float dz = __ldg(&pos[s * 3 + 2]) - __ldg(&pos[d * 3 + 2]);
        float r = sqrtf(dx * dx + dy * dy + dz * dz + 1e-10f);
        r = fmaxf(r, 1e-4f);
        if (r < 6.0f) {
            valid = true;
            float u = r * (1.0f / 6.0f);
            cut = expf(-u * u / (1.0f - u * u));
            tt = 2.0f * expf(-r) - 1.0f;
            tt = fminf(fmaxf(tt, -1.0f), 1.0f);
            if (PASS == 1) {
                zs = __ldg(&Z[s]);
                float zdf = (float)__ldg(&Z[d]);
                float zsf = (float)zs;
                float aa = 0.46853332f / (powf(zdf, 0.23f) + powf(zsf, 0.23f) + 1e-10f);
                float ra = r / aa;
                float phi = 0.18175f * expf(-3.1998f  * ra)
                          + 0.50986f * expf(-0.94229f * ra)
                          + 0.28022f * expf(-0.4029f  * ra)
                          + 0.02817f * expf(-0.20162f * ra);
                float ep = 0.5f * 14.399645f * zdf * zsf / r * phi * cut;
                atomicAdd(&g_epair[d], ep);
            }
        }
    }

    // ---- feature phase: compacted, 4 valid edges per iteration ----
    unsigned mask = __ballot_sync(0xffffffffu, valid);
    int cnt = __popc(mask);
    int oct = lane >> 3;
    int fg = (lane & 7) * 4;
    const float4* w4 = reinterpret_cast<const float4*>(&sW[fg]);  // row stride: 8 float4

    for (int base = 0; base < cnt; base += 4) {
        int k = base + oct;
        bool active = (k < cnt);
        unsigned srcLane = active ? __fns(mask, 0, k + 1) : 0u;
        float tte  = __shfl_sync(0xffffffffu, tt,  srcLane);
        float cute = __shfl_sync(0xffffffffu, cut, srcLane);
        int   de   = __shfl_sync(0xffffffffu, d,   srcLane);
        int   se   = __shfl_sync(0xffffffffu, s,   srcLane);
        int   ze   = 0;
        if (PASS == 1) ze = __shfl_sync(0xffffffffu, zs, srcLane);
        if (!active) continue;

        // g[f] = sum_k T_k(tte) * W[k][f], then * cut
        float4 w = w4[0];
        float a0 = w.x, a1 = w.y, a2 = w.z, a3 = w.w;
        w = w4[8];
        a0 = fmaf(tte, w.x, a0); a1 = fmaf(tte, w.y, a1);
        a2 = fmaf(tte, w.z, a2); a3 = fmaf(tte, w.w, a3);
        float Tp = 1.0f, Tc = tte;
#pragma unroll
        for (int kk = 2; kk < KDIM; kk++) {
            float Tn = 2.0f * tte * Tc - Tp; Tp = Tc; Tc = Tn;
            w = w4[8 * kk];
            a0 = fmaf(Tn, w.x, a0); a1 = fmaf(Tn, w.y, a1);
            a2 = fmaf(Tn, w.z, a2); a3 = fmaf(Tn, w.w, a3);
        }
        a0 *= cute; a1 *= cute; a2 *= cute; a3 *= cute;

        float4 v;
        if (PASS == 1) {
            v = __ldg(reinterpret_cast<const float4*>(&emb[ze * FDIM + fg]));
            red4(&g_x0[de * FDIM + fg], a0 * v.x, a1 * v.y, a2 * v.z, a3 * v.w);
        } else {
            v = *reinterpret_cast<const float4*>(&g_x0[se * FDIM + fg]);
            red4(&g_y[de * FDIM + fg], a0 * v.x, a1 * v.y, a2 * v.z, a3 * v.w);
        }
    }
}

// x0 = x0 + (h * silu(h)) @ W2_0,  h = x0 @ W1_0   (in place on g_x0)
__global__ void __launch_bounds__(64) mlp1_kernel(
    const float* __restrict__ W1, const float* __restrict__ W2, int N) {
    __shared__ float s1[FDIM * FDIM], s2[FDIM * FDIM];
    for (int i = threadIdx.x; i < FDIM * FDIM; i += blockDim.x) {
        s1[i] = W1[i]; s2[i] = W2[i];
    }
    __syncthreads();
    int n = blockIdx.x * blockDim.x + threadIdx.x;
    if (n >= N) return;

    float x[FDIM], t[FDIM];
#pragma unroll
    for (int f = 0; f < FDIM; f += 4) {
        float4 v = *reinterpret_cast<const float4*>(&g_x0[n * FDIM + f]);
        x[f] = v.x; x[f + 1] = v.y; x[f + 2] = v.z; x[f + 3] = v.w;
    }
#pragma unroll
    for (int gb = 0; gb < FDIM; gb += 4) {
        float h0 = 0.f, h1 = 0.f, h2 = 0.f, h3 = 0.f;
#pragma unroll
        for (int f = 0; f < FDIM; f++) {
            float4 wv = *reinterpret_cast<const float4*>(&s1[f * FDIM + gb]);
            h0 = fmaf(x[f], wv.x, h0); h1 = fmaf(x[f], wv.y, h1);
            h2 = fmaf(x[f], wv.z, h2); h3 = fmaf(x[f], wv.w, h3);
        }
        // h * silu(h) = h^2 * sigmoid(h)
        t[gb]     = h0 * h0 / (1.0f + expf(-h0));
        t[gb + 1] = h1 * h1 / (1.0f + expf(-h1));
        t[gb + 2] = h2 * h2 / (1.0f + expf(-h2));
        t[gb + 3] = h3 * h3 / (1.0f + expf(-h3));
    }
#pragma unroll
    for (int gb = 0; gb < FDIM; gb += 4) {
        float o0 = x[gb], o1 = x[gb + 1], o2 = x[gb + 2], o3 = x[gb + 3];
#pragma unroll
        for (int f = 0; f < FDIM; f++) {
            float4 wv = *reinterpret_cast<const float4*>(&s2[f * FDIM + gb]);
            o0 = fmaf(t[f], wv.x, o0); o1 = fmaf(t[f], wv.y, o1);
            o2 = fmaf(t[f], wv.z, o2); o3 = fmaf(t[f], wv.w, o3);
        }
        *reinterpret_cast<float4*>(&g_x0[n * FDIM + gb]) = make_float4(o0, o1, o2, o3);
    }
}

// y2 = y + silu(y@W1_1)@W2_1 ; e = y2.w_out + b_out[Z] + epair; masked; atomic into out[batch]
__global__ void __launch_bounds__(64) final_kernel(
    const float* __restrict__ W1, const float* __restrict__ W2,
    const float* __restrict__ wout, const float* __restrict__ bout,
    const int* __restrict__ Z, const int* __restrict__ bseg,
    const float* __restrict__ amask, const float* __restrict__ bmask,
    float* __restrict__ out, int N) {
    __shared__ float s1[FDIM * FDIM], s2[FDIM * FDIM], sw[FDIM];
    for (int i = threadIdx.x; i < FDIM * FDIM; i += blockDim.x) {
        s1[i] = W1[i]; s2[i] = W2[i];
    }
    if (threadIdx.x < FDIM) sw[threadIdx.x] = wout[threadIdx.x];
    __syncthreads();
    int n = blockIdx.x * blockDim.x + threadIdx.x;
    if (n >= N) return;

    float y[FDIM], t[FDIM];
#pragma unroll
    for (int f = 0; f < FDIM; f += 4) {
        float4 v = *reinterpret_cast<const float4*>(&g_y[n * FDIM + f]);
        y[f] = v.x; y[f + 1] = v.y; y[f + 2] = v.z; y[f + 3] = v.w;
    }
#pragma unroll
    for (int gb = 0; gb < FDIM; gb += 4) {
        float h0 = 0.f, h1 = 0.f, h2 = 0.f, h3 = 0.f;
#pragma unroll
        for (int f = 0; f < FDIM; f++) {
            float4 wv = *reinterpret_cast<const float4*>(&s1[f * FDIM + gb]);
            h0 = fmaf(y[f], wv.x, h0); h1 = fmaf(y[f], wv.y, h1);
            h2 = fmaf(y[f], wv.z, h2); h3 = fmaf(y[f], wv.w, h3);
        }
        // silu(h) = h * sigmoid(h)
        t[gb]     = h0 / (1.0f + expf(-h0));
        t[gb + 1] = h1 / (1.0f + expf(-h1));
        t[gb + 2] = h2 / (1.0f + expf(-h2));
        t[gb + 3] = h3 / (1.0f + expf(-h3));
    }
    float e = 0.0f;
#pragma unroll
    for (int gb = 0; gb < FDIM; gb += 4) {
        float o0 = y[gb], o1 = y[gb + 1], o2 = y[gb + 2], o3 = y[gb + 3];
#pragma unroll
        for (int f = 0; f < FDIM; f++) {
            float4 wv = *reinterpret_cast<const float4*>(&s2[f * FDIM + gb]);
            o0 = fmaf(t[f], wv.x, o0); o1 = fmaf(t[f], wv.y, o1);
            o2 = fmaf(t[f], wv.z, o2); o3 = fmaf(t[f], wv.w, o3);
        }
        e = fmaf(o0, sw[gb], e);
        e = fmaf(o1, sw[gb + 1], e);
        e = fmaf(o2, sw[gb + 2], e);
        e = fmaf(o3, sw[gb + 3], e);
    }
    e += __ldg(&bout[__ldg(&Z[n])]) + g_epair[n];
    e *= __ldg(&amask[n]);
    int b = __ldg(&bseg[n]);
    atomicAdd(&out[b], e * __ldg(&bmask[b]));
}

extern "C" void kernel_launch(void* const* d_in, const int* in_sizes, int n_in,
                              void* d_out, int out_size) {
    const int*   Z     = (const int*)d_in[0];
    const float* pos   = (const float*)d_in[1];
    const int*   dst   = (const int*)d_in[2];
    const int*   src   = (const int*)d_in[3];
    const int*   bseg  = (const int*)d_in[4];
    // 'batch_size' may or may not be materialized as a size-1 input at index 5.
    int off = (in_sizes[5] == 1) ? 1 : 0;
    const float* bmask = (const float*)d_in[5 + off];
    const float* amask = (const float*)d_in[6 + off];
    const float* emb   = (const float*)d_in[7 + off];
    const float* Wr1_0 = (const float*)d_in[8 + off];
    const float* Wr2_0 = (const float*)d_in[9 + off];
    const float* W1_0  = (const float*)d_in[10 + off];
    const float* W2_0  = (const float*)d_in[11 + off];
    const float* Wr1_1 = (const float*)d_in[12 + off];
    const float* W1_1  = (const float*)d_in[13 + off];
    const float* W2_1  = (const float*)d_in[14 + off];
    const float* wout  = (const float*)d_in[15 + off];
    const float* bout  = (const float*)d_in[16 + off];

    int N = in_sizes[0];
    int E = in_sizes[2];
    int B = out_size;
    float* out = (float*)d_out;

    init_kernel<<<(N * FDIM / 4 + 255) / 256, 256>>>(out, B, Wr1_0, Wr2_0, N);

    int eblocks = (E + 255) / 256;  // 256 edges per 256-thread block (32 edges/warp)
    edge_kernel<1><<<eblocks, 256>>>(pos, dst, src, Z, emb, nullptr, E);

    mlp1_kernel<<<(N + 63) / 64, 64>>>(W1_0, W2_0, N);

    edge_kernel<2><<<eblocks, 256>>>(pos, dst, src, Z, emb, Wr1_1, E);

    final_kernel<<<(N + 63) / 64, 64>>>(W1_1, W2_1, wout, bout, Z, bseg,
                                        amask, bmask, out, N);
}